// round 16
// baseline (speedup 1.0000x reference)
#include <cuda_runtime.h>
#include <math.h>
#include <stdint.h>

#define DEPTH   6
#define D_MODEL 512
#define N_HEADS 8
#define D_HEAD  64
#define D_FF    2048
#define SEQ_T   2048
#define VOCAB   256
#define BB      2
#define MROWS   (BB * SEQ_T)     /* 4096 */
#define EPS_LN  1e-5f
#define NQT     (SEQ_T / 64)     /* 32 q-tiles */

// ---------------------------------------------------------------------------
// Static device scratch
// ---------------------------------------------------------------------------
__device__ float g_h   [MROWS * D_MODEL];
__device__ float g_ln  [MROWS * D_MODEL];
__device__ float g_qkv [MROWS * 3 * D_MODEL];
__device__ float g_attn[MROWS * D_MODEL];
__device__ float g_ff  [MROWS * D_FF];

// ---------------------------------------------------------------------------
// Helpers
// ---------------------------------------------------------------------------
__device__ __forceinline__ unsigned f2tf(float f) {
    unsigned u;
    asm("cvt.rna.tf32.f32 %0, %1;" : "=r"(u) : "f"(f));
    return u;
}

__device__ __forceinline__ float gelu_exact(float x) {
    return 0.5f * x * (1.0f + erff(x * 0.70710678118654752f));
}

// ---------------------------------------------------------------------------
// Embedding
// ---------------------------------------------------------------------------
__global__ void embed_kernel(const int* __restrict__ x,
                             const float* __restrict__ tok,
                             const float* __restrict__ pos,
                             float* __restrict__ h) {
    int i = blockIdx.x * blockDim.x + threadIdx.x;
    if (i >= MROWS * D_MODEL) return;
    int d   = i & (D_MODEL - 1);
    int row = i >> 9;
    int t   = row & (SEQ_T - 1);
    int tok_id = x[row];
    h[i] = tok[tok_id * D_MODEL + d] + pos[t * D_MODEL + d];
}

// ---------------------------------------------------------------------------
// LayerNorm: warp per row, shfl reductions, no smem/syncs. 8 rows/block.
// ---------------------------------------------------------------------------
__global__ __launch_bounds__(256)
void ln_kernel(const float* __restrict__ in,
               const float* __restrict__ w,
               const float* __restrict__ b,
               float* __restrict__ out) {
    int lane = threadIdx.x & 31;
    int row  = blockIdx.x * 8 + (threadIdx.x >> 5);
    const float* xr = in + (size_t)row * D_MODEL;

    float4 v[4];
    float sum = 0.0f;
    #pragma unroll
    for (int c = 0; c < 4; c++) {
        v[c] = *(const float4*)&xr[lane * 4 + c * 128];
        sum += (v[c].x + v[c].y) + (v[c].z + v[c].w);
    }
    #pragma unroll
    for (int off = 16; off > 0; off >>= 1)
        sum += __shfl_xor_sync(0xffffffffu, sum, off);
    float mu = sum * (1.0f / D_MODEL);

    float var = 0.0f;
    #pragma unroll
    for (int c = 0; c < 4; c++) {
        float d0 = v[c].x - mu, d1 = v[c].y - mu;
        float d2 = v[c].z - mu, d3 = v[c].w - mu;
        var += (d0 * d0 + d1 * d1) + (d2 * d2 + d3 * d3);
    }
    #pragma unroll
    for (int off = 16; off > 0; off >>= 1)
        var += __shfl_xor_sync(0xffffffffu, var, off);
    float rstd = rsqrtf(var * (1.0f / D_MODEL) + EPS_LN);

    float* orow = out + (size_t)row * D_MODEL;
    #pragma unroll
    for (int c = 0; c < 4; c++) {
        float4 wv = *(const float4*)&w[lane * 4 + c * 128];
        float4 bv = *(const float4*)&b[lane * 4 + c * 128];
        float4 o;
        o.x = (v[c].x - mu) * rstd * wv.x + bv.x;
        o.y = (v[c].y - mu) * rstd * wv.y + bv.y;
        o.z = (v[c].z - mu) * rstd * wv.z + bv.z;
        o.w = (v[c].w - mu) * rstd * wv.w + bv.w;
        *(float4*)&orow[lane * 4 + c * 128] = o;
    }
}

// ---------------------------------------------------------------------------
// tf32 mma.sync GEMM, 128x128 tile (R8 proven). For wide-N GEMMs (qkv, fc1).
// ---------------------------------------------------------------------------
#define GSTRIDE 136
#define GBUF    (32 * GSTRIDE)
#define GEMM_SMEM (4 * GBUF * 4)

template <int EPI>
__global__ __launch_bounds__(256, 2)
void gemm_tf32_kernel(const float* __restrict__ X,
                      const float* __restrict__ W,
                      float* __restrict__ Y,
                      int M, int N, int K) {
    extern __shared__ unsigned smu[];
    unsigned* Xs = smu;
    unsigned* Ws = smu + 2 * GBUF;

    int tid = threadIdx.x;
    int w = tid >> 5, l = tid & 31;
    int wm = w & 3;
    int wn = w >> 2;
    int g = l >> 2, t = l & 3;
    int rowBase = blockIdx.y * 128;
    int colBase = blockIdx.x * 128;

    int lm = tid & 127;
    int ks = (tid >> 7) * 16;
    const float* xp = X + (size_t)(rowBase + lm) * K + ks;
    const float* wp = W + (size_t)(colBase + lm) * K + ks;

    float acc[2][8][4];
    #pragma unroll
    for (int i = 0; i < 2; i++)
        #pragma unroll
        for (int j = 0; j < 8; j++)
            #pragma unroll
            for (int c = 0; c < 4; c++) acc[i][j][c] = 0.0f;

    float4 rx[4], rw[4];
    #pragma unroll
    for (int c = 0; c < 4; c++) {
        rx[c] = *(const float4*)(xp + c * 4);
        rw[c] = *(const float4*)(wp + c * 4);
    }
    #pragma unroll
    for (int c = 0; c < 4; c++) {
        int kr = ks + c * 4;
        Xs[(kr + 0) * GSTRIDE + lm] = f2tf(rx[c].x);
        Xs[(kr + 1) * GSTRIDE + lm] = f2tf(rx[c].y);
        Xs[(kr + 2) * GSTRIDE + lm] = f2tf(rx[c].z);
        Xs[(kr + 3) * GSTRIDE + lm] = f2tf(rx[c].w);
        Ws[(kr + 0) * GSTRIDE + lm] = f2tf(rw[c].x);
        Ws[(kr + 1) * GSTRIDE + lm] = f2tf(rw[c].y);
        Ws[(kr + 2) * GSTRIDE + lm] = f2tf(rw[c].z);
        Ws[(kr + 3) * GSTRIDE + lm] = f2tf(rw[c].w);
    }
    __syncthreads();

    int nBK = K >> 5;
    for (int kt = 0; kt < nBK; kt++) {
        int cur = kt & 1;
        bool more = (kt + 1 < nBK);
        if (more) {
            int koff = (kt + 1) << 5;
            #pragma unroll
            for (int c = 0; c < 4; c++) {
                rx[c] = *(const float4*)(xp + koff + c * 4);
                rw[c] = *(const float4*)(wp + koff + c * 4);
            }
        }

        const unsigned* Xc = Xs + cur * GBUF;
        const unsigned* Wc = Ws + cur * GBUF;
        #pragma unroll
        for (int kb = 0; kb < 32; kb += 8) {
            unsigned a[2][4];
            #pragma unroll
            for (int i = 0; i < 2; i++) {
                int mB = wm * 32 + i * 16;
                a[i][0] = Xc[(kb + t)     * GSTRIDE + mB + g];
                a[i][1] = Xc[(kb + t)     * GSTRIDE + mB + g + 8];
                a[i][2] = Xc[(kb + t + 4) * GSTRIDE + mB + g];
                a[i][3] = Xc[(kb + t + 4) * GSTRIDE + mB + g + 8];
            }
            #pragma unroll
            for (int j = 0; j < 8; j++) {
                int nB = wn * 64 + j * 8;
                unsigned b0 = Wc[(kb + t)     * GSTRIDE + nB + g];
                unsigned b1 = Wc[(kb + t + 4) * GSTRIDE + nB + g];
                #pragma unroll
                for (int i = 0; i < 2; i++) {
                    asm volatile(
                        "mma.sync.aligned.m16n8k8.row.col.f32.tf32.tf32.f32 "
                        "{%0,%1,%2,%3}, {%4,%5,%6,%7}, {%8,%9}, {%0,%1,%2,%3};"
                        : "+f"(acc[i][j][0]), "+f"(acc[i][j][1]),
                          "+f"(acc[i][j][2]), "+f"(acc[i][j][3])
                        : "r"(a[i][0]), "r"(a[i][1]), "r"(a[i][2]), "r"(a[i][3]),
                          "r"(b0), "r"(b1));
                }
            }
        }

        if (more) {
            unsigned* Xa = Xs + (cur ^ 1) * GBUF;
            unsigned* Wa = Ws + (cur ^ 1) * GBUF;
            #pragma unroll
            for (int c = 0; c < 4; c++) {
                int kr = ks + c * 4;
                Xa[(kr + 0) * GSTRIDE + lm] = f2tf(rx[c].x);
                Xa[(kr + 1) * GSTRIDE + lm] = f2tf(rx[c].y);
                Xa[(kr + 2) * GSTRIDE + lm] = f2tf(rx[c].z);
                Xa[(kr + 3) * GSTRIDE + lm] = f2tf(rx[c].w);
                Wa[(kr + 0) * GSTRIDE + lm] = f2tf(rw[c].x);
                Wa[(kr + 1) * GSTRIDE + lm] = f2tf(rw[c].y);
                Wa[(kr + 2) * GSTRIDE + lm] = f2tf(rw[c].z);
                Wa[(kr + 3) * GSTRIDE + lm] = f2tf(rw[c].w);
            }
            __syncthreads();
        }
    }

    #pragma unroll
    for (int i = 0; i < 2; i++) {
        int r0 = rowBase + wm * 32 + i * 16 + g;
        #pragma unroll
        for (int j = 0; j < 8; j++) {
            int n = colBase + wn * 64 + j * 8 + 2 * t;
            size_t i0 = (size_t)r0 * N + n;
            size_t i1 = (size_t)(r0 + 8) * N + n;
            if (EPI == 0) {
                *(float2*)&Y[i0] = make_float2(acc[i][j][0], acc[i][j][1]);
                *(float2*)&Y[i1] = make_float2(acc[i][j][2], acc[i][j][3]);
            } else if (EPI == 1) {
                float2 y0 = *(float2*)&Y[i0];
                float2 y1 = *(float2*)&Y[i1];
                y0.x += acc[i][j][0]; y0.y += acc[i][j][1];
                y1.x += acc[i][j][2]; y1.y += acc[i][j][3];
                *(float2*)&Y[i0] = y0;
                *(float2*)&Y[i1] = y1;
            } else {
                *(float2*)&Y[i0] = make_float2(gelu_exact(acc[i][j][0]),
                                               gelu_exact(acc[i][j][1]));
                *(float2*)&Y[i1] = make_float2(gelu_exact(acc[i][j][2]),
                                               gelu_exact(acc[i][j][3]));
            }
        }
    }
}

// ---------------------------------------------------------------------------
// tf32 mma.sync GEMM, 64x128 tile — for narrow-N GEMMs (proj, fc2, head).
// Doubles block count: better wave occupancy. Same warp math, 1 m16 per warp.
// ---------------------------------------------------------------------------
#define XSTR    72
#define XBUF    (32 * XSTR)
#define G64_SMEM ((2 * XBUF + 2 * GBUF) * 4)

template <int EPI>
__global__ __launch_bounds__(256, 2)
void gemm64_tf32_kernel(const float* __restrict__ X,
                        const float* __restrict__ W,
                        float* __restrict__ Y,
                        int M, int N, int K) {
    extern __shared__ unsigned smu[];
    unsigned* Xs = smu;                  // [2][32][XSTR]
    unsigned* Ws = smu + 2 * XBUF;       // [2][32][GSTRIDE]

    int tid = threadIdx.x;
    int w = tid >> 5, l = tid & 31;
    int wm = w & 3;
    int wn = w >> 2;
    int g = l >> 2, t = l & 3;
    int rowBase = blockIdx.y * 64;
    int colBase = blockIdx.x * 128;

    // X staging: 64 rows x 32 k; thread -> row lmx, k block of 8
    int lmx = tid & 63;
    int ksx = (tid >> 6) * 8;
    const float* xp = X + (size_t)(rowBase + lmx) * K + ksx;
    // W staging: 128 rows x 32 k (as in 128-tile kernel)
    int lmw = tid & 127;
    int ksw = (tid >> 7) * 16;
    const float* wp = W + (size_t)(colBase + lmw) * K + ksw;

    float acc[8][4];
    #pragma unroll
    for (int j = 0; j < 8; j++)
        #pragma unroll
        for (int c = 0; c < 4; c++) acc[j][c] = 0.0f;

    float4 rx[2], rw[4];
    #pragma unroll
    for (int c = 0; c < 2; c++) rx[c] = *(const float4*)(xp + c * 4);
    #pragma unroll
    for (int c = 0; c < 4; c++) rw[c] = *(const float4*)(wp + c * 4);

    #pragma unroll
    for (int c = 0; c < 2; c++) {
        int kr = ksx + c * 4;
        Xs[(kr + 0) * XSTR + lmx] = f2tf(rx[c].x);
        Xs[(kr + 1) * XSTR + lmx] = f2tf(rx[c].y);
        Xs[(kr + 2) * XSTR + lmx] = f2tf(rx[c].z);
        Xs[(kr + 3) * XSTR + lmx] = f2tf(rx[c].w);
    }
    #pragma unroll
    for (int c = 0; c < 4; c++) {
        int kr = ksw + c * 4;
        Ws[(kr + 0) * GSTRIDE + lmw] = f2tf(rw[c].x);
        Ws[(kr + 1) * GSTRIDE + lmw] = f2tf(rw[c].y);
        Ws[(kr + 2) * GSTRIDE + lmw] = f2tf(rw[c].z);
        Ws[(kr + 3) * GSTRIDE + lmw] = f2tf(rw[c].w);
    }
    __syncthreads();

    int nBK = K >> 5;
    for (int kt = 0; kt < nBK; kt++) {
        int cur = kt & 1;
        bool more = (kt + 1 < nBK);
        if (more) {
            int koff = (kt + 1) << 5;
            #pragma unroll
            for (int c = 0; c < 2; c++) rx[c] = *(const float4*)(xp + koff + c * 4);
            #pragma unroll
            for (int c = 0; c < 4; c++) rw[c] = *(const float4*)(wp + koff + c * 4);
        }

        const unsigned* Xc = Xs + cur * XBUF;
        const unsigned* Wc = Ws + cur * GBUF;
        #pragma unroll
        for (int kb = 0; kb < 32; kb += 8) {
            unsigned a0, a1, a2, a3;
            {
                int mB = wm * 16;
                a0 = Xc[(kb + t)     * XSTR + mB + g];
                a1 = Xc[(kb + t)     * XSTR + mB + g + 8];
                a2 = Xc[(kb + t + 4) * XSTR + mB + g];
                a3 = Xc[(kb + t + 4) * XSTR + mB + g + 8];
            }
            #pragma unroll
            for (int j = 0; j < 8; j++) {
                int nB = wn * 64 + j * 8;
                unsigned b0 = Wc[(kb + t)     * GSTRIDE + nB + g];
                unsigned b1 = Wc[(kb + t + 4) * GSTRIDE + nB + g];
                asm volatile(
                    "mma.sync.aligned.m16n8k8.row.col.f32.tf32.tf32.f32 "
                    "{%0,%1,%2,%3}, {%4,%5,%6,%7}, {%8,%9}, {%0,%1,%2,%3};"
                    : "+f"(acc[j][0]), "+f"(acc[j][1]),
                      "+f"(acc[j][2]), "+f"(acc[j][3])
                    : "r"(a0), "r"(a1), "r"(a2), "r"(a3),
                      "r"(b0), "r"(b1));
            }
        }

        if (more) {
            unsigned* Xa = Xs + (cur ^ 1) * XBUF;
            unsigned* Wa = Ws + (cur ^ 1) * GBUF;
            #pragma unroll
            for (int c = 0; c < 2; c++) {
                int kr = ksx + c * 4;
                Xa[(kr + 0) * XSTR + lmx] = f2tf(rx[c].x);
                Xa[(kr + 1) * XSTR + lmx] = f2tf(rx[c].y);
                Xa[(kr + 2) * XSTR + lmx] = f2tf(rx[c].z);
                Xa[(kr + 3) * XSTR + lmx] = f2tf(rx[c].w);
            }
            #pragma unroll
            for (int c = 0; c < 4; c++) {
                int kr = ksw + c * 4;
                Wa[(kr + 0) * GSTRIDE + lmw] = f2tf(rw[c].x);
                Wa[(kr + 1) * GSTRIDE + lmw] = f2tf(rw[c].y);
                Wa[(kr + 2) * GSTRIDE + lmw] = f2tf(rw[c].z);
                Wa[(kr + 3) * GSTRIDE + lmw] = f2tf(rw[c].w);
            }
            __syncthreads();
        }
    }

    int r0 = rowBase + wm * 16 + g;
    #pragma unroll
    for (int j = 0; j < 8; j++) {
        int n = colBase + wn * 64 + j * 8 + 2 * t;
        size_t i0 = (size_t)r0 * N + n;
        size_t i1 = (size_t)(r0 + 8) * N + n;
        if (EPI == 0) {
            *(float2*)&Y[i0] = make_float2(acc[j][0], acc[j][1]);
            *(float2*)&Y[i1] = make_float2(acc[j][2], acc[j][3]);
        } else if (EPI == 1) {
            float2 y0 = *(float2*)&Y[i0];
            float2 y1 = *(float2*)&Y[i1];
            y0.x += acc[j][0]; y0.y += acc[j][1];
            y1.x += acc[j][2]; y1.y += acc[j][3];
            *(float2*)&Y[i0] = y0;
            *(float2*)&Y[i1] = y1;
        } else {
            *(float2*)&Y[i0] = make_float2(gelu_exact(acc[j][0]),
                                           gelu_exact(acc[j][1]));
            *(float2*)&Y[i1] = make_float2(gelu_exact(acc[j][2]),
                                           gelu_exact(acc[j][3]));
        }
    }
}

// ---------------------------------------------------------------------------
// Flash attention, balanced pairing (R9 proven config)
// ---------------------------------------------------------------------------
__global__ __launch_bounds__(256)
void fattn_kernel(const float* __restrict__ qkv,
                  float* __restrict__ out) {
    int qp = blockIdx.x;
    int h  = blockIdx.y;
    int b  = blockIdx.z;
    int tid = threadIdx.x;
    int tx = tid & 15;
    int ty = tid >> 4;

    __shared__ float Qs[64][64];
    __shared__ float KPs[64][64];
    __shared__ float Vs[64][64];

    int lq = tid & 63;
    int dg = (tid >> 6) * 16;

    #pragma unroll 1
    for (int ph = 0; ph < 2; ph++) {
        int qt = ph ? (NQT - 1 - qp) : qp;

        {
            const float* qb = qkv + ((size_t)(b * SEQ_T + qt * 64 + lq)) * (3 * D_MODEL)
                            + h * D_HEAD;
            #pragma unroll
            for (int it = 0; it < 4; it++) {
                float4 v = *(const float4*)(qb + dg + it * 4);
                Qs[dg + it * 4 + 0][lq] = v.x;
                Qs[dg + it * 4 + 1][lq] = v.y;
                Qs[dg + it * 4 + 2][lq] = v.z;
                Qs[dg + it * 4 + 3][lq] = v.w;
            }
        }

        float accO[4][4];
        #pragma unroll
        for (int i = 0; i < 4; i++)
            #pragma unroll
            for (int j = 0; j < 4; j++) accO[i][j] = 0.0f;
        float m_i[4] = {-1e30f, -1e30f, -1e30f, -1e30f};
        float l_i[4] = {0.0f, 0.0f, 0.0f, 0.0f};

        __syncthreads();

        for (int kt = 0; kt <= qt; kt++) {
            {
                const float* kb = qkv + ((size_t)(b * SEQ_T + kt * 64 + lq)) * (3 * D_MODEL)
                                + D_MODEL + h * D_HEAD;
                #pragma unroll
                for (int it = 0; it < 4; it++) {
                    float4 v = *(const float4*)(kb + dg + it * 4);
                    KPs[dg + it * 4 + 0][lq] = v.x;
                    KPs[dg + it * 4 + 1][lq] = v.y;
                    KPs[dg + it * 4 + 2][lq] = v.z;
                    KPs[dg + it * 4 + 3][lq] = v.w;
                }
                #pragma unroll
                for (int it = 0; it < 4; it++) {
                    int f = it * 256 + tid;
                    int kk = f >> 4;
                    int d4 = (f & 15) * 4;
                    const float* vb = qkv + ((size_t)(b * SEQ_T + kt * 64 + kk)) * (3 * D_MODEL)
                                    + 2 * D_MODEL + h * D_HEAD + d4;
                    float4 v = *(const float4*)vb;
                    *(float4*)&Vs[kk][d4] = v;
                }
            }
            __syncthreads();

            float s[4][4];
            #pragma unroll
            for (int i = 0; i < 4; i++)
                #pragma unroll
                for (int j = 0; j < 4; j++) s[i][j] = 0.0f;

            #pragma unroll 8
            for (int d = 0; d < 64; d++) {
                float4 qa = *(const float4*)&Qs[d][ty * 4];
                float4 ka = *(const float4*)&KPs[d][tx * 4];
                float a[4] = {qa.x, qa.y, qa.z, qa.w};
                float kv[4] = {ka.x, ka.y, ka.z, ka.w};
                #pragma unroll
                for (int i = 0; i < 4; i++)
                    #pragma unroll
                    for (int j = 0; j < 4; j++)
                        s[i][j] += a[i] * kv[j];
            }

            #pragma unroll
            for (int i = 0; i < 4; i++)
                #pragma unroll
                for (int j = 0; j < 4; j++) {
                    s[i][j] *= 0.125f;
                    if (kt == qt) {
                        int gq = ty * 4 + i;
                        int gk = tx * 4 + j;
                        if (gk > gq) s[i][j] = -1e30f;
                    }
                }

            float p[4][4];
            #pragma unroll
            for (int i = 0; i < 4; i++) {
                float rmax = fmaxf(fmaxf(s[i][0], s[i][1]), fmaxf(s[i][2], s[i][3]));
                #pragma unroll
                for (int off = 1; off < 16; off <<= 1)
                    rmax = fmaxf(rmax, __shfl_xor_sync(0xffffffffu, rmax, off));
                float m_new = fmaxf(m_i[i], rmax);
                float scale = __expf(m_i[i] - m_new);
                float rs = 0.0f;
                #pragma unroll
                for (int j = 0; j < 4; j++) {
                    p[i][j] = __expf(s[i][j] - m_new);
                    rs += p[i][j];
                }
                #pragma unroll
                for (int off = 1; off < 16; off <<= 1)
                    rs += __shfl_xor_sync(0xffffffffu, rs, off);
                l_i[i] = l_i[i] * scale + rs;
                m_i[i] = m_new;
                #pragma unroll
                for (int j = 0; j < 4; j++) accO[i][j] *= scale;
            }

            __syncthreads();

            #pragma unroll
            for (int i = 0; i < 4; i++)
                *(float4*)&KPs[ty * 4 + i][tx * 4] =
                    make_float4(p[i][0], p[i][1], p[i][2], p[i][3]);
            __syncthreads();

            #pragma unroll 4
            for (int k = 0; k < 64; k++) {
                float4 vv = *(const float4*)&Vs[k][tx * 4];
                float v4[4] = {vv.x, vv.y, vv.z, vv.w};
                #pragma unroll
                for (int i = 0; i < 4; i++) {
                    float pk = KPs[ty * 4 + i][k];
                    #pragma unroll
                    for (int j = 0; j < 4; j++)
                        accO[i][j] += pk * v4[j];
                }
            }
            __syncthreads();
        }

        #pragma unroll
        for (int i = 0; i < 4; i++) {
            float inv = 1.0f / l_i[i];
            size_t row = (size_t)(b * SEQ_T + qt * 64 + ty * 4 + i);
            float* orow = out + row * D_MODEL + h * D_HEAD + tx * 4;
            orow[0] = accO[i][0] * inv;
            orow[1] = accO[i][1] * inv;
            orow[2] = accO[i][2] * inv;
            orow[3] = accO[i][3] * inv;
        }
    }
}

// ---------------------------------------------------------------------------
// Host launcher
// ---------------------------------------------------------------------------
extern "C" void kernel_launch(void* const* d_in, const int* in_sizes, int n_in,
                              void* d_out, int out_size) {
    const int*   x       = (const int*)  d_in[0];
    const float* tok_emb = (const float*)d_in[1];
    const float* pos_emb = (const float*)d_in[2];
    const float* qkv_w   = (const float*)d_in[3];
    const float* proj_w  = (const float*)d_in[4];
    const float* ln1_w   = (const float*)d_in[5];
    const float* ln1_b   = (const float*)d_in[6];
    const float* ln2_w   = (const float*)d_in[7];
    const float* ln2_b   = (const float*)d_in[8];
    const float* fc1_w   = (const float*)d_in[9];
    const float* fc2_w   = (const float*)d_in[10];
    const float* lnf_w   = (const float*)d_in[11];
    const float* lnf_b   = (const float*)d_in[12];
    const float* head_w  = (const float*)d_in[13];
    float* out = (float*)d_out;

    float *ph, *pln, *pqkv, *pattn, *pff;
    cudaGetSymbolAddress((void**)&ph,    g_h);
    cudaGetSymbolAddress((void**)&pln,   g_ln);
    cudaGetSymbolAddress((void**)&pqkv,  g_qkv);
    cudaGetSymbolAddress((void**)&pattn, g_attn);
    cudaGetSymbolAddress((void**)&pff,   g_ff);

    cudaFuncSetAttribute(gemm_tf32_kernel<0>,
                         cudaFuncAttributeMaxDynamicSharedMemorySize, GEMM_SMEM);
    cudaFuncSetAttribute(gemm_tf32_kernel<2>,
                         cudaFuncAttributeMaxDynamicSharedMemorySize, GEMM_SMEM);
    cudaFuncSetAttribute(gemm64_tf32_kernel<0>,
                         cudaFuncAttributeMaxDynamicSharedMemorySize, G64_SMEM);
    cudaFuncSetAttribute(gemm64_tf32_kernel<1>,
                         cudaFuncAttributeMaxDynamicSharedMemorySize, G64_SMEM);

    embed_kernel<<<(MROWS * D_MODEL + 255) / 256, 256>>>(x, tok_emb, pos_emb, ph);

    for (int l = 0; l < DEPTH; l++) {
        const float* qw  = qkv_w  + (size_t)l * 3 * D_MODEL * D_MODEL;
        const float* pw  = proj_w + (size_t)l * D_MODEL * D_MODEL;
        const float* f1w = fc1_w  + (size_t)l * D_FF * D_MODEL;
        const float* f2w = fc2_w  + (size_t)l * D_MODEL * D_FF;

        ln_kernel<<<MROWS / 8, 256>>>(ph, ln1_w + l * D_MODEL, ln1_b + l * D_MODEL, pln);

        gemm_tf32_kernel<0><<<dim3(3 * D_MODEL / 128, MROWS / 128), 256, GEMM_SMEM>>>(
            pln, qw, pqkv, MROWS, 3 * D_MODEL, D_MODEL);

        fattn_kernel<<<dim3(NQT / 2, N_HEADS, BB), 256>>>(pqkv, pattn);

        gemm64_tf32_kernel<1><<<dim3(D_MODEL / 128, MROWS / 64), 256, G64_SMEM>>>(
            pattn, pw, ph, MROWS, D_MODEL, D_MODEL);

        ln_kernel<<<MROWS / 8, 256>>>(ph, ln2_w + l * D_MODEL, ln2_b + l * D_MODEL, pln);

        gemm_tf32_kernel<2><<<dim3(D_FF / 128, MROWS / 128), 256, GEMM_SMEM>>>(
            pln, f1w, pff, MROWS, D_FF, D_MODEL);

        gemm64_tf32_kernel<1><<<dim3(D_MODEL / 128, MROWS / 64), 256, G64_SMEM>>>(
            pff, f2w, ph, MROWS, D_MODEL, D_FF);
    }

    ln_kernel<<<MROWS / 8, 256>>>(ph, lnf_w, lnf_b, pln);
    gemm64_tf32_kernel<0><<<dim3(VOCAB / 128, MROWS / 64), 256, G64_SMEM>>>(
        pln, head_w, out, MROWS, VOCAB, D_MODEL);

    (void)in_sizes; (void)n_in; (void)out_size;
}

// round 17
// speedup vs baseline: 1.1140x; 1.1140x over previous
#include <cuda_runtime.h>
#include <math.h>
#include <stdint.h>

#define DEPTH   6
#define D_MODEL 512
#define N_HEADS 8
#define D_HEAD  64
#define D_FF    2048
#define SEQ_T   2048
#define VOCAB   256
#define BB      2
#define MROWS   (BB * SEQ_T)     /* 4096 */
#define EPS_LN  1e-5f
#define NQT     (SEQ_T / 64)     /* 32 q-tiles */

// ---------------------------------------------------------------------------
// Static device scratch
// ---------------------------------------------------------------------------
__device__ float g_h   [MROWS * D_MODEL];
__device__ float g_ln  [MROWS * D_MODEL];
__device__ float g_qkv [MROWS * 3 * D_MODEL];
__device__ float g_attn[MROWS * D_MODEL];
__device__ float g_ff  [MROWS * D_FF];

// ---------------------------------------------------------------------------
// Helpers
// ---------------------------------------------------------------------------
__device__ __forceinline__ unsigned f2tf(float f) {
    unsigned u;
    asm("cvt.rna.tf32.f32 %0, %1;" : "=r"(u) : "f"(f));
    return u;
}

__device__ __forceinline__ float gelu_exact(float x) {
    return 0.5f * x * (1.0f + erff(x * 0.70710678118654752f));
}

// ---------------------------------------------------------------------------
// Embedding
// ---------------------------------------------------------------------------
__global__ void embed_kernel(const int* __restrict__ x,
                             const float* __restrict__ tok,
                             const float* __restrict__ pos,
                             float* __restrict__ h) {
    int i = blockIdx.x * blockDim.x + threadIdx.x;
    if (i >= MROWS * D_MODEL) return;
    int d   = i & (D_MODEL - 1);
    int row = i >> 9;
    int t   = row & (SEQ_T - 1);
    int tok_id = x[row];
    h[i] = tok[tok_id * D_MODEL + d] + pos[t * D_MODEL + d];
}

// ---------------------------------------------------------------------------
// LayerNorm: warp per row, shfl reductions. 8 rows/block.
// ---------------------------------------------------------------------------
__global__ __launch_bounds__(256)
void ln_kernel(const float* __restrict__ in,
               const float* __restrict__ w,
               const float* __restrict__ b,
               float* __restrict__ out) {
    int lane = threadIdx.x & 31;
    int row  = blockIdx.x * 8 + (threadIdx.x >> 5);
    const float* xr = in + (size_t)row * D_MODEL;

    float4 v[4];
    float sum = 0.0f;
    #pragma unroll
    for (int c = 0; c < 4; c++) {
        v[c] = *(const float4*)&xr[lane * 4 + c * 128];
        sum += (v[c].x + v[c].y) + (v[c].z + v[c].w);
    }
    #pragma unroll
    for (int off = 16; off > 0; off >>= 1)
        sum += __shfl_xor_sync(0xffffffffu, sum, off);
    float mu = sum * (1.0f / D_MODEL);

    float var = 0.0f;
    #pragma unroll
    for (int c = 0; c < 4; c++) {
        float d0 = v[c].x - mu, d1 = v[c].y - mu;
        float d2 = v[c].z - mu, d3 = v[c].w - mu;
        var += (d0 * d0 + d1 * d1) + (d2 * d2 + d3 * d3);
    }
    #pragma unroll
    for (int off = 16; off > 0; off >>= 1)
        var += __shfl_xor_sync(0xffffffffu, var, off);
    float rstd = rsqrtf(var * (1.0f / D_MODEL) + EPS_LN);

    float* orow = out + (size_t)row * D_MODEL;
    #pragma unroll
    for (int c = 0; c < 4; c++) {
        float4 wv = *(const float4*)&w[lane * 4 + c * 128];
        float4 bv = *(const float4*)&b[lane * 4 + c * 128];
        float4 o;
        o.x = (v[c].x - mu) * rstd * wv.x + bv.x;
        o.y = (v[c].y - mu) * rstd * wv.y + bv.y;
        o.z = (v[c].z - mu) * rstd * wv.z + bv.z;
        o.w = (v[c].w - mu) * rstd * wv.w + bv.w;
        *(float4*)&orow[lane * 4 + c * 128] = o;
    }
}

// ---------------------------------------------------------------------------
// tf32 mma.sync GEMM, 128x128 tile (R8 proven). EPI: 0 store, 2 gelu.
// ---------------------------------------------------------------------------
#define GSTRIDE 136
#define GBUF    (32 * GSTRIDE)
#define GEMM_SMEM (4 * GBUF * 4)

template <int EPI>
__global__ __launch_bounds__(256, 2)
void gemm_tf32_kernel(const float* __restrict__ X,
                      const float* __restrict__ W,
                      float* __restrict__ Y,
                      int M, int N, int K) {
    extern __shared__ unsigned smu[];
    unsigned* Xs = smu;
    unsigned* Ws = smu + 2 * GBUF;

    int tid = threadIdx.x;
    int w = tid >> 5, l = tid & 31;
    int wm = w & 3;
    int wn = w >> 2;
    int g = l >> 2, t = l & 3;
    int rowBase = blockIdx.y * 128;
    int colBase = blockIdx.x * 128;

    int lm = tid & 127;
    int ks = (tid >> 7) * 16;
    const float* xp = X + (size_t)(rowBase + lm) * K + ks;
    const float* wp = W + (size_t)(colBase + lm) * K + ks;

    float acc[2][8][4];
    #pragma unroll
    for (int i = 0; i < 2; i++)
        #pragma unroll
        for (int j = 0; j < 8; j++)
            #pragma unroll
            for (int c = 0; c < 4; c++) acc[i][j][c] = 0.0f;

    float4 rx[4], rw[4];
    #pragma unroll
    for (int c = 0; c < 4; c++) {
        rx[c] = *(const float4*)(xp + c * 4);
        rw[c] = *(const float4*)(wp + c * 4);
    }
    #pragma unroll
    for (int c = 0; c < 4; c++) {
        int kr = ks + c * 4;
        Xs[(kr + 0) * GSTRIDE + lm] = f2tf(rx[c].x);
        Xs[(kr + 1) * GSTRIDE + lm] = f2tf(rx[c].y);
        Xs[(kr + 2) * GSTRIDE + lm] = f2tf(rx[c].z);
        Xs[(kr + 3) * GSTRIDE + lm] = f2tf(rx[c].w);
        Ws[(kr + 0) * GSTRIDE + lm] = f2tf(rw[c].x);
        Ws[(kr + 1) * GSTRIDE + lm] = f2tf(rw[c].y);
        Ws[(kr + 2) * GSTRIDE + lm] = f2tf(rw[c].z);
        Ws[(kr + 3) * GSTRIDE + lm] = f2tf(rw[c].w);
    }
    __syncthreads();

    int nBK = K >> 5;
    for (int kt = 0; kt < nBK; kt++) {
        int cur = kt & 1;
        bool more = (kt + 1 < nBK);
        if (more) {
            int koff = (kt + 1) << 5;
            #pragma unroll
            for (int c = 0; c < 4; c++) {
                rx[c] = *(const float4*)(xp + koff + c * 4);
                rw[c] = *(const float4*)(wp + koff + c * 4);
            }
        }

        const unsigned* Xc = Xs + cur * GBUF;
        const unsigned* Wc = Ws + cur * GBUF;
        #pragma unroll
        for (int kb = 0; kb < 32; kb += 8) {
            unsigned a[2][4];
            #pragma unroll
            for (int i = 0; i < 2; i++) {
                int mB = wm * 32 + i * 16;
                a[i][0] = Xc[(kb + t)     * GSTRIDE + mB + g];
                a[i][1] = Xc[(kb + t)     * GSTRIDE + mB + g + 8];
                a[i][2] = Xc[(kb + t + 4) * GSTRIDE + mB + g];
                a[i][3] = Xc[(kb + t + 4) * GSTRIDE + mB + g + 8];
            }
            #pragma unroll
            for (int j = 0; j < 8; j++) {
                int nB = wn * 64 + j * 8;
                unsigned b0 = Wc[(kb + t)     * GSTRIDE + nB + g];
                unsigned b1 = Wc[(kb + t + 4) * GSTRIDE + nB + g];
                #pragma unroll
                for (int i = 0; i < 2; i++) {
                    asm volatile(
                        "mma.sync.aligned.m16n8k8.row.col.f32.tf32.tf32.f32 "
                        "{%0,%1,%2,%3}, {%4,%5,%6,%7}, {%8,%9}, {%0,%1,%2,%3};"
                        : "+f"(acc[i][j][0]), "+f"(acc[i][j][1]),
                          "+f"(acc[i][j][2]), "+f"(acc[i][j][3])
                        : "r"(a[i][0]), "r"(a[i][1]), "r"(a[i][2]), "r"(a[i][3]),
                          "r"(b0), "r"(b1));
                }
            }
        }

        if (more) {
            unsigned* Xa = Xs + (cur ^ 1) * GBUF;
            unsigned* Wa = Ws + (cur ^ 1) * GBUF;
            #pragma unroll
            for (int c = 0; c < 4; c++) {
                int kr = ks + c * 4;
                Xa[(kr + 0) * GSTRIDE + lm] = f2tf(rx[c].x);
                Xa[(kr + 1) * GSTRIDE + lm] = f2tf(rx[c].y);
                Xa[(kr + 2) * GSTRIDE + lm] = f2tf(rx[c].z);
                Xa[(kr + 3) * GSTRIDE + lm] = f2tf(rx[c].w);
                Wa[(kr + 0) * GSTRIDE + lm] = f2tf(rw[c].x);
                Wa[(kr + 1) * GSTRIDE + lm] = f2tf(rw[c].y);
                Wa[(kr + 2) * GSTRIDE + lm] = f2tf(rw[c].z);
                Wa[(kr + 3) * GSTRIDE + lm] = f2tf(rw[c].w);
            }
            __syncthreads();
        }
    }

    #pragma unroll
    for (int i = 0; i < 2; i++) {
        int r0 = rowBase + wm * 32 + i * 16 + g;
        #pragma unroll
        for (int j = 0; j < 8; j++) {
            int n = colBase + wn * 64 + j * 8 + 2 * t;
            size_t i0 = (size_t)r0 * N + n;
            size_t i1 = (size_t)(r0 + 8) * N + n;
            if (EPI == 0) {
                *(float2*)&Y[i0] = make_float2(acc[i][j][0], acc[i][j][1]);
                *(float2*)&Y[i1] = make_float2(acc[i][j][2], acc[i][j][3]);
            } else if (EPI == 1) {
                float2 y0 = *(float2*)&Y[i0];
                float2 y1 = *(float2*)&Y[i1];
                y0.x += acc[i][j][0]; y0.y += acc[i][j][1];
                y1.x += acc[i][j][2]; y1.y += acc[i][j][3];
                *(float2*)&Y[i0] = y0;
                *(float2*)&Y[i1] = y1;
            } else {
                *(float2*)&Y[i0] = make_float2(gelu_exact(acc[i][j][0]),
                                               gelu_exact(acc[i][j][1]));
                *(float2*)&Y[i1] = make_float2(gelu_exact(acc[i][j][2]),
                                               gelu_exact(acc[i][j][3]));
            }
        }
    }
}

// ---------------------------------------------------------------------------
// Split-K variant: grid.z slices of KS each; partials atomicAdd'ed into Y
// (Y already holds the residual). Same tile/pipeline as gemm_tf32_kernel.
// ---------------------------------------------------------------------------
__global__ __launch_bounds__(256, 2)
void gemm_sk_kernel(const float* __restrict__ X,
                    const float* __restrict__ W,
                    float* __restrict__ Y,
                    int M, int N, int K, int KS) {
    extern __shared__ unsigned smu[];
    unsigned* Xs = smu;
    unsigned* Ws = smu + 2 * GBUF;

    int tid = threadIdx.x;
    int w = tid >> 5, l = tid & 31;
    int wm = w & 3;
    int wn = w >> 2;
    int g = l >> 2, t = l & 3;
    int rowBase = blockIdx.y * 128;
    int colBase = blockIdx.x * 128;
    int kOff = blockIdx.z * KS;

    int lm = tid & 127;
    int ks = (tid >> 7) * 16;
    const float* xp = X + (size_t)(rowBase + lm) * K + kOff + ks;
    const float* wp = W + (size_t)(colBase + lm) * K + kOff + ks;

    float acc[2][8][4];
    #pragma unroll
    for (int i = 0; i < 2; i++)
        #pragma unroll
        for (int j = 0; j < 8; j++)
            #pragma unroll
            for (int c = 0; c < 4; c++) acc[i][j][c] = 0.0f;

    float4 rx[4], rw[4];
    #pragma unroll
    for (int c = 0; c < 4; c++) {
        rx[c] = *(const float4*)(xp + c * 4);
        rw[c] = *(const float4*)(wp + c * 4);
    }
    #pragma unroll
    for (int c = 0; c < 4; c++) {
        int kr = ks + c * 4;
        Xs[(kr + 0) * GSTRIDE + lm] = f2tf(rx[c].x);
        Xs[(kr + 1) * GSTRIDE + lm] = f2tf(rx[c].y);
        Xs[(kr + 2) * GSTRIDE + lm] = f2tf(rx[c].z);
        Xs[(kr + 3) * GSTRIDE + lm] = f2tf(rx[c].w);
        Ws[(kr + 0) * GSTRIDE + lm] = f2tf(rw[c].x);
        Ws[(kr + 1) * GSTRIDE + lm] = f2tf(rw[c].y);
        Ws[(kr + 2) * GSTRIDE + lm] = f2tf(rw[c].z);
        Ws[(kr + 3) * GSTRIDE + lm] = f2tf(rw[c].w);
    }
    __syncthreads();

    int nBK = KS >> 5;
    for (int kt = 0; kt < nBK; kt++) {
        int cur = kt & 1;
        bool more = (kt + 1 < nBK);
        if (more) {
            int koff = (kt + 1) << 5;
            #pragma unroll
            for (int c = 0; c < 4; c++) {
                rx[c] = *(const float4*)(xp + koff + c * 4);
                rw[c] = *(const float4*)(wp + koff + c * 4);
            }
        }

        const unsigned* Xc = Xs + cur * GBUF;
        const unsigned* Wc = Ws + cur * GBUF;
        #pragma unroll
        for (int kb = 0; kb < 32; kb += 8) {
            unsigned a[2][4];
            #pragma unroll
            for (int i = 0; i < 2; i++) {
                int mB = wm * 32 + i * 16;
                a[i][0] = Xc[(kb + t)     * GSTRIDE + mB + g];
                a[i][1] = Xc[(kb + t)     * GSTRIDE + mB + g + 8];
                a[i][2] = Xc[(kb + t + 4) * GSTRIDE + mB + g];
                a[i][3] = Xc[(kb + t + 4) * GSTRIDE + mB + g + 8];
            }
            #pragma unroll
            for (int j = 0; j < 8; j++) {
                int nB = wn * 64 + j * 8;
                unsigned b0 = Wc[(kb + t)     * GSTRIDE + nB + g];
                unsigned b1 = Wc[(kb + t + 4) * GSTRIDE + nB + g];
                #pragma unroll
                for (int i = 0; i < 2; i++) {
                    asm volatile(
                        "mma.sync.aligned.m16n8k8.row.col.f32.tf32.tf32.f32 "
                        "{%0,%1,%2,%3}, {%4,%5,%6,%7}, {%8,%9}, {%0,%1,%2,%3};"
                        : "+f"(acc[i][j][0]), "+f"(acc[i][j][1]),
                          "+f"(acc[i][j][2]), "+f"(acc[i][j][3])
                        : "r"(a[i][0]), "r"(a[i][1]), "r"(a[i][2]), "r"(a[i][3]),
                          "r"(b0), "r"(b1));
                }
            }
        }

        if (more) {
            unsigned* Xa = Xs + (cur ^ 1) * GBUF;
            unsigned* Wa = Ws + (cur ^ 1) * GBUF;
            #pragma unroll
            for (int c = 0; c < 4; c++) {
                int kr = ks + c * 4;
                Xa[(kr + 0) * GSTRIDE + lm] = f2tf(rx[c].x);
                Xa[(kr + 1) * GSTRIDE + lm] = f2tf(rx[c].y);
                Xa[(kr + 2) * GSTRIDE + lm] = f2tf(rx[c].z);
                Xa[(kr + 3) * GSTRIDE + lm] = f2tf(rx[c].w);
                Wa[(kr + 0) * GSTRIDE + lm] = f2tf(rw[c].x);
                Wa[(kr + 1) * GSTRIDE + lm] = f2tf(rw[c].y);
                Wa[(kr + 2) * GSTRIDE + lm] = f2tf(rw[c].z);
                Wa[(kr + 3) * GSTRIDE + lm] = f2tf(rw[c].w);
            }
            __syncthreads();
        }
    }

    #pragma unroll
    for (int i = 0; i < 2; i++) {
        int r0 = rowBase + wm * 32 + i * 16 + g;
        #pragma unroll
        for (int j = 0; j < 8; j++) {
            int n = colBase + wn * 64 + j * 8 + 2 * t;
            size_t i0 = (size_t)r0 * N + n;
            size_t i1 = (size_t)(r0 + 8) * N + n;
            atomicAdd(&Y[i0],     acc[i][j][0]);
            atomicAdd(&Y[i0 + 1], acc[i][j][1]);
            atomicAdd(&Y[i1],     acc[i][j][2]);
            atomicAdd(&Y[i1 + 1], acc[i][j][3]);
        }
    }
}

// ---------------------------------------------------------------------------
// Flash attention, balanced pairing (R9 proven config)
// ---------------------------------------------------------------------------
__global__ __launch_bounds__(256)
void fattn_kernel(const float* __restrict__ qkv,
                  float* __restrict__ out) {
    int qp = blockIdx.x;
    int h  = blockIdx.y;
    int b  = blockIdx.z;
    int tid = threadIdx.x;
    int tx = tid & 15;
    int ty = tid >> 4;

    __shared__ float Qs[64][64];
    __shared__ float KPs[64][64];
    __shared__ float Vs[64][64];

    int lq = tid & 63;
    int dg = (tid >> 6) * 16;

    #pragma unroll 1
    for (int ph = 0; ph < 2; ph++) {
        int qt = ph ? (NQT - 1 - qp) : qp;

        {
            const float* qb = qkv + ((size_t)(b * SEQ_T + qt * 64 + lq)) * (3 * D_MODEL)
                            + h * D_HEAD;
            #pragma unroll
            for (int it = 0; it < 4; it++) {
                float4 v = *(const float4*)(qb + dg + it * 4);
                Qs[dg + it * 4 + 0][lq] = v.x;
                Qs[dg + it * 4 + 1][lq] = v.y;
                Qs[dg + it * 4 + 2][lq] = v.z;
                Qs[dg + it * 4 + 3][lq] = v.w;
            }
        }

        float accO[4][4];
        #pragma unroll
        for (int i = 0; i < 4; i++)
            #pragma unroll
            for (int j = 0; j < 4; j++) accO[i][j] = 0.0f;
        float m_i[4] = {-1e30f, -1e30f, -1e30f, -1e30f};
        float l_i[4] = {0.0f, 0.0f, 0.0f, 0.0f};

        __syncthreads();

        for (int kt = 0; kt <= qt; kt++) {
            {
                const float* kb = qkv + ((size_t)(b * SEQ_T + kt * 64 + lq)) * (3 * D_MODEL)
                                + D_MODEL + h * D_HEAD;
                #pragma unroll
                for (int it = 0; it < 4; it++) {
                    float4 v = *(const float4*)(kb + dg + it * 4);
                    KPs[dg + it * 4 + 0][lq] = v.x;
                    KPs[dg + it * 4 + 1][lq] = v.y;
                    KPs[dg + it * 4 + 2][lq] = v.z;
                    KPs[dg + it * 4 + 3][lq] = v.w;
                }
                #pragma unroll
                for (int it = 0; it < 4; it++) {
                    int f = it * 256 + tid;
                    int kk = f >> 4;
                    int d4 = (f & 15) * 4;
                    const float* vb = qkv + ((size_t)(b * SEQ_T + kt * 64 + kk)) * (3 * D_MODEL)
                                    + 2 * D_MODEL + h * D_HEAD + d4;
                    float4 v = *(const float4*)vb;
                    *(float4*)&Vs[kk][d4] = v;
                }
            }
            __syncthreads();

            float s[4][4];
            #pragma unroll
            for (int i = 0; i < 4; i++)
                #pragma unroll
                for (int j = 0; j < 4; j++) s[i][j] = 0.0f;

            #pragma unroll 8
            for (int d = 0; d < 64; d++) {
                float4 qa = *(const float4*)&Qs[d][ty * 4];
                float4 ka = *(const float4*)&KPs[d][tx * 4];
                float a[4] = {qa.x, qa.y, qa.z, qa.w};
                float kv[4] = {ka.x, ka.y, ka.z, ka.w};
                #pragma unroll
                for (int i = 0; i < 4; i++)
                    #pragma unroll
                    for (int j = 0; j < 4; j++)
                        s[i][j] += a[i] * kv[j];
            }

            #pragma unroll
            for (int i = 0; i < 4; i++)
                #pragma unroll
                for (int j = 0; j < 4; j++) {
                    s[i][j] *= 0.125f;
                    if (kt == qt) {
                        int gq = ty * 4 + i;
                        int gk = tx * 4 + j;
                        if (gk > gq) s[i][j] = -1e30f;
                    }
                }

            float p[4][4];
            #pragma unroll
            for (int i = 0; i < 4; i++) {
                float rmax = fmaxf(fmaxf(s[i][0], s[i][1]), fmaxf(s[i][2], s[i][3]));
                #pragma unroll
                for (int off = 1; off < 16; off <<= 1)
                    rmax = fmaxf(rmax, __shfl_xor_sync(0xffffffffu, rmax, off));
                float m_new = fmaxf(m_i[i], rmax);
                float scale = __expf(m_i[i] - m_new);
                float rs = 0.0f;
                #pragma unroll
                for (int j = 0; j < 4; j++) {
                    p[i][j] = __expf(s[i][j] - m_new);
                    rs += p[i][j];
                }
                #pragma unroll
                for (int off = 1; off < 16; off <<= 1)
                    rs += __shfl_xor_sync(0xffffffffu, rs, off);
                l_i[i] = l_i[i] * scale + rs;
                m_i[i] = m_new;
                #pragma unroll
                for (int j = 0; j < 4; j++) accO[i][j] *= scale;
            }

            __syncthreads();

            #pragma unroll
            for (int i = 0; i < 4; i++)
                *(float4*)&KPs[ty * 4 + i][tx * 4] =
                    make_float4(p[i][0], p[i][1], p[i][2], p[i][3]);
            __syncthreads();

            #pragma unroll 4
            for (int k = 0; k < 64; k++) {
                float4 vv = *(const float4*)&Vs[k][tx * 4];
                float v4[4] = {vv.x, vv.y, vv.z, vv.w};
                #pragma unroll
                for (int i = 0; i < 4; i++) {
                    float pk = KPs[ty * 4 + i][k];
                    #pragma unroll
                    for (int j = 0; j < 4; j++)
                        accO[i][j] += pk * v4[j];
                }
            }
            __syncthreads();
        }

        #pragma unroll
        for (int i = 0; i < 4; i++) {
            float inv = 1.0f / l_i[i];
            size_t row = (size_t)(b * SEQ_T + qt * 64 + ty * 4 + i);
            float* orow = out + row * D_MODEL + h * D_HEAD + tx * 4;
            orow[0] = accO[i][0] * inv;
            orow[1] = accO[i][1] * inv;
            orow[2] = accO[i][2] * inv;
            orow[3] = accO[i][3] * inv;
        }
    }
}

// ---------------------------------------------------------------------------
// Host launcher
// ---------------------------------------------------------------------------
extern "C" void kernel_launch(void* const* d_in, const int* in_sizes, int n_in,
                              void* d_out, int out_size) {
    const int*   x       = (const int*)  d_in[0];
    const float* tok_emb = (const float*)d_in[1];
    const float* pos_emb = (const float*)d_in[2];
    const float* qkv_w   = (const float*)d_in[3];
    const float* proj_w  = (const float*)d_in[4];
    const float* ln1_w   = (const float*)d_in[5];
    const float* ln1_b   = (const float*)d_in[6];
    const float* ln2_w   = (const float*)d_in[7];
    const float* ln2_b   = (const float*)d_in[8];
    const float* fc1_w   = (const float*)d_in[9];
    const float* fc2_w   = (const float*)d_in[10];
    const float* lnf_w   = (const float*)d_in[11];
    const float* lnf_b   = (const float*)d_in[12];
    const float* head_w  = (const float*)d_in[13];
    float* out = (float*)d_out;

    float *ph, *pln, *pqkv, *pattn, *pff;
    cudaGetSymbolAddress((void**)&ph,    g_h);
    cudaGetSymbolAddress((void**)&pln,   g_ln);
    cudaGetSymbolAddress((void**)&pqkv,  g_qkv);
    cudaGetSymbolAddress((void**)&pattn, g_attn);
    cudaGetSymbolAddress((void**)&pff,   g_ff);

    cudaFuncSetAttribute(gemm_tf32_kernel<0>,
                         cudaFuncAttributeMaxDynamicSharedMemorySize, GEMM_SMEM);
    cudaFuncSetAttribute(gemm_tf32_kernel<2>,
                         cudaFuncAttributeMaxDynamicSharedMemorySize, GEMM_SMEM);
    cudaFuncSetAttribute(gemm_sk_kernel,
                         cudaFuncAttributeMaxDynamicSharedMemorySize, GEMM_SMEM);

    embed_kernel<<<(MROWS * D_MODEL + 255) / 256, 256>>>(x, tok_emb, pos_emb, ph);

    for (int l = 0; l < DEPTH; l++) {
        const float* qw  = qkv_w  + (size_t)l * 3 * D_MODEL * D_MODEL;
        const float* pw  = proj_w + (size_t)l * D_MODEL * D_MODEL;
        const float* f1w = fc1_w  + (size_t)l * D_FF * D_MODEL;
        const float* f2w = fc2_w  + (size_t)l * D_MODEL * D_FF;

        ln_kernel<<<MROWS / 8, 256>>>(ph, ln1_w + l * D_MODEL, ln1_b + l * D_MODEL, pln);

        gemm_tf32_kernel<0><<<dim3(3 * D_MODEL / 128, MROWS / 128), 256, GEMM_SMEM>>>(
            pln, qw, pqkv, MROWS, 3 * D_MODEL, D_MODEL);

        fattn_kernel<<<dim3(NQT / 2, N_HEADS, BB), 256>>>(pqkv, pattn);

        // proj: split-K 2 -> 256 blocks, atomic accumulate into residual
        gemm_sk_kernel<<<dim3(D_MODEL / 128, MROWS / 128, 2), 256, GEMM_SMEM>>>(
            pattn, pw, ph, MROWS, D_MODEL, D_MODEL, D_MODEL / 2);

        ln_kernel<<<MROWS / 8, 256>>>(ph, ln2_w + l * D_MODEL, ln2_b + l * D_MODEL, pln);

        gemm_tf32_kernel<2><<<dim3(D_FF / 128, MROWS / 128), 256, GEMM_SMEM>>>(
            pln, f1w, pff, MROWS, D_FF, D_MODEL);

        // fc2: split-K 4 -> 512 blocks, atomic accumulate into residual
        gemm_sk_kernel<<<dim3(D_MODEL / 128, MROWS / 128, 4), 256, GEMM_SMEM>>>(
            pff, f2w, ph, MROWS, D_MODEL, D_FF, D_FF / 4);
    }

    ln_kernel<<<MROWS / 8, 256>>>(ph, lnf_w, lnf_b, pln);
    gemm_tf32_kernel<0><<<dim3(VOCAB / 128, MROWS / 128), 256, GEMM_SMEM>>>(
        pln, head_w, out, MROWS, VOCAB, D_MODEL);

    (void)in_sizes; (void)n_in; (void)out_size;
}